// round 11
// baseline (speedup 1.0000x reference)
#include <cuda_runtime.h>
#include <math.h>
#include <stdint.h>

#define BB 2
#define SS 2048
#define NH 16
#define DHD 128
#define DRP 64
#define DMODEL 2048
#define DC 512
#define DCOMP 768
#define NTOK (BB*SS)

#define N0 (DC + DCOMP + NH*DRP)     // 2304  (kv_c | q_cmp | k_r)
#define QCMP_OFF DC                  // 512
#define KR_OFF0 (DC + DCOMP)         // 1280
#define N2 (DMODEL + NH*DRP)         // 3072  (q_c | q_r)
#define QR_OFF DMODEL                // 2048

// ---------------- scratch (static device globals; no allocation) ----------------
__device__ float g_xt  [NTOK*DMODEL];
__device__ float g_big0[NTOK*N0];
__device__ float g_kvup[NTOK*DMODEL];
__device__ float g_big2[NTOK*N2];
__device__ float g_attn[NTOK*DMODEL];
__device__ float g_bt0 [N0*DMODEL];
__device__ float g_wuT [DMODEL*DC];
__device__ float g_bt2 [N2*DCOMP];
__device__ float g_woT [DMODEL*DMODEL];
__device__ float g_bias0[N0];
__device__ float g_bias2[N2];

__device__ __forceinline__ uint32_t f2tf32(float x) {
    uint32_t r;
    asm("cvt.rna.tf32.f32 %0, %1;" : "=r"(r) : "f"(x));
    return r;
}
__device__ __forceinline__ float roundtf(float x) {
    return __uint_as_float(f2tf32(x));
}
__device__ __forceinline__ uint32_t smem_u32(const void* p) {
    uint32_t a;
    asm("{ .reg .u64 t; cvta.to.shared.u64 t, %1; cvt.u32.u64 %0, t; }"
        : "=r"(a) : "l"(p));
    return a;
}

#define MMA_TF32(d0,d1,d2,d3, a0,a1,a2,a3, b0,b1) \
    asm volatile( \
        "mma.sync.aligned.m16n8k8.row.col.f32.tf32.tf32.f32 " \
        "{%0,%1,%2,%3}, {%4,%5,%6,%7}, {%8,%9}, {%0,%1,%2,%3};" \
        : "+f"(d0), "+f"(d1), "+f"(d2), "+f"(d3) \
        : "r"(a0), "r"(a1), "r"(a2), "r"(a3), "r"(b0), "r"(b1))

#define LDSM_X4(r0,r1,r2,r3, addr) \
    asm volatile("ldmatrix.sync.aligned.m8n8.x4.shared.b16 {%0,%1,%2,%3}, [%4];" \
        : "=r"(r0), "=r"(r1), "=r"(r2), "=r"(r3) : "r"(addr))

#define CP_ASYNC16(dst, src) \
    asm volatile("cp.async.cg.shared.global [%0], [%1], 16;" \
                 :: "r"(dst), "l"(src))
#define CP_COMMIT() asm volatile("cp.async.commit_group;" ::: "memory")
#define CP_WAIT1()  asm volatile("cp.async.wait_group 1;" ::: "memory")
#define CP_WAIT0()  asm volatile("cp.async.wait_group 0;" ::: "memory")

// ================= helpers =================
__global__ void round_tf32_kernel(const float* __restrict__ in,
                                  float* __restrict__ out, int n4)
{
    int i = blockIdx.x * blockDim.x + threadIdx.x;
    if (i >= n4) return;
    float4 v = ((const float4*)in)[i];
    v.x = roundtf(v.x); v.y = roundtf(v.y);
    v.z = roundtf(v.z); v.w = roundtf(v.w);
    ((float4*)out)[i] = v;
}

__global__ void concat_bias3(float* __restrict__ dst,
                             const float* __restrict__ a, int na,
                             const float* __restrict__ b, int nb,
                             const float* __restrict__ c, int nc)
{
    int i = blockIdx.x * blockDim.x + threadIdx.x;
    if (i < na) dst[i] = a[i];
    else if (i < na + nb) dst[i] = b[i - na];
    else if (i < na + nb + nc) dst[i] = c[i - na - nb];
}

__global__ void transpose_multi(
    const float* __restrict__ in0, int nsz0,
    const float* __restrict__ in1, int nsz1,
    const float* __restrict__ in2, int nsz2,
    float* __restrict__ out, int K)
{
    __shared__ float t[32][33];
    int gn = blockIdx.x * 32;
    int k0 = blockIdx.y * 32;
    const float* src; int N; int col0;
    if (gn < nsz0)              { src = in0; N = nsz0; col0 = gn; }
    else if (gn < nsz0 + nsz1)  { src = in1; N = nsz1; col0 = gn - nsz0; }
    else                        { src = in2; N = nsz2; col0 = gn - nsz0 - nsz1; }
    int tx = threadIdx.x, ty = threadIdx.y;  // (32, 8)
    #pragma unroll
    for (int i = 0; i < 4; ++i)
        t[ty + 8*i][tx] = src[(size_t)(k0 + ty + 8*i) * N + col0 + tx];
    __syncthreads();
    #pragma unroll
    for (int i = 0; i < 4; ++i)
        out[(size_t)(gn + ty + 8*i) * K + k0 + tx] = roundtf(t[tx][ty + 8*i]);
}

// ================= cp.async 3-stage tf32 GEMM body (LDSM fragments) =========
#define GBK 32
#define GSTG 3
#define GLDW 36
#define GSTG_WORDS (256 * GLDW)
#define GEMM_SMEM (GSTG * GSTG_WORDS * 4)    // 110,592 B; x2 CTA

__device__ __forceinline__ void gemm_body(
    const float* __restrict__ A, int lda,
    const float* __restrict__ Bt,
    const float* __restrict__ bias,
    float* __restrict__ C, int ldc,
    int K, int row0, int col0,
    uint32_t* gsm, int round_out)
{
    const int tid  = threadIdx.x;
    const int lane = tid & 31;
    const int wid  = tid >> 5;
    const int wm = wid >> 2, wn = wid & 3;
    const int gr = lane >> 2, gc = lane & 3;
    const int wr = wm * 64,  wc = wn * 32;
    const int l8 = lane & 7;
    const int t4 = lane >> 3;          // ldmatrix tile index 0..3

    const float* Ag = A  + (size_t)row0 * lda;
    const float* Bg = Bt + (size_t)col0 * K;

    const int crow = tid >> 3;
    const int ccol = (tid & 7) * 4;
    const uint32_t smbase = smem_u32(gsm);

    // ldmatrix per-lane byte offsets (within a stage)
    uint32_t aoff[4], boff[2];
    #pragma unroll
    for (int i = 0; i < 4; ++i)
        aoff[i] = (uint32_t)(((wr + 16*i + 8*(t4 & 1) + l8) * GLDW
                              + 4*(t4 >> 1)) * 4);
    #pragma unroll
    for (int p = 0; p < 2; ++p)
        boff[p] = (uint32_t)((128 * GLDW +
                              (wc + 16*p + 8*(t4 >> 1) + l8) * GLDW
                              + 4*(t4 & 1)) * 4);

    const int niter = K / GBK;

    auto issue_stage = [&](int it) {
        const int s = it % GSTG;
        const int ko = it * GBK;
        uint32_t as = smbase + (uint32_t)(s * GSTG_WORDS) * 4u;
        uint32_t bs = as + (uint32_t)(128 * GLDW) * 4u;
        #pragma unroll
        for (int c = 0; c < 4; ++c) {
            int r = crow + 32 * c;
            CP_ASYNC16(as + (uint32_t)(r * GLDW + ccol) * 4u,
                       Ag + (size_t)r * lda + ko + ccol);
            CP_ASYNC16(bs + (uint32_t)(r * GLDW + ccol) * 4u,
                       Bg + (size_t)r * K + ko + ccol);
        }
    };

    float acc[4][4][4];
    #pragma unroll
    for (int i = 0; i < 4; ++i)
        #pragma unroll
        for (int j = 0; j < 4; ++j)
            #pragma unroll
            for (int c = 0; c < 4; ++c) acc[i][j][c] = 0.f;

    issue_stage(0); CP_COMMIT();
    issue_stage(1); CP_COMMIT();

    for (int it = 0; it < niter; ++it) {
        CP_WAIT1();
        __syncthreads();

        if (it + 2 < niter) issue_stage(it + 2);
        CP_COMMIT();

        const uint32_t stg = smbase + (uint32_t)((it % GSTG) * GSTG_WORDS) * 4u;

        #pragma unroll
        for (int ks = 0; ks < 4; ++ks) {
            const uint32_t kb4 = (uint32_t)(ks * 8 * 4);
            uint32_t a[4][4], b[4][2];
            #pragma unroll
            for (int i = 0; i < 4; ++i)
                LDSM_X4(a[i][0], a[i][1], a[i][2], a[i][3], stg + aoff[i] + kb4);
            LDSM_X4(b[0][0], b[0][1], b[1][0], b[1][1], stg + boff[0] + kb4);
            LDSM_X4(b[2][0], b[2][1], b[3][0], b[3][1], stg + boff[1] + kb4);
            #pragma unroll
            for (int i = 0; i < 4; ++i)
                #pragma unroll
                for (int j = 0; j < 4; ++j)
                    MMA_TF32(acc[i][j][0], acc[i][j][1], acc[i][j][2], acc[i][j][3],
                             a[i][0], a[i][1], a[i][2], a[i][3], b[j][0], b[j][1]);
        }
    }

    #pragma unroll
    for (int j = 0; j < 4; ++j) {
        int c = col0 + wc + 8*j + 2*gc;
        float bv0 = bias[c], bv1 = bias[c + 1];
        #pragma unroll
        for (int i = 0; i < 4; ++i) {
            int r = row0 + wr + 16*i + gr;
            float f0 = acc[i][j][0] + bv0, f1 = acc[i][j][1] + bv1;
            float f2 = acc[i][j][2] + bv0, f3 = acc[i][j][3] + bv1;
            if (round_out) {
                f0 = roundtf(f0); f1 = roundtf(f1);
                f2 = roundtf(f2); f3 = roundtf(f3);
            }
            *(float2*)(C + (size_t)r * ldc + c)       = make_float2(f0, f1);
            *(float2*)(C + (size_t)(r + 8) * ldc + c) = make_float2(f2, f3);
        }
    }
}

__global__ __launch_bounds__(256, 2) void gemm_cp(
    const float* __restrict__ A, int lda,
    const float* __restrict__ Bt,
    const float* __restrict__ bias,
    float* __restrict__ C, int ldc,
    int K, int round_out)
{
    extern __shared__ uint32_t gsm[];
    gemm_body(A, lda, Bt, bias, C, ldc, K,
              blockIdx.y * 128, blockIdx.x * 128, gsm, round_out);
}

__global__ __launch_bounds__(256, 2) void gemm_dual(
    const float* __restrict__ A0, int lda0, const float* __restrict__ Bt0,
    const float* __restrict__ bias0, float* __restrict__ C0, int ldc0, int K0,
    const float* __restrict__ A1, int lda1, const float* __restrict__ Bt1,
    const float* __restrict__ bias1, float* __restrict__ C1, int ldc1, int K1,
    int split)
{
    extern __shared__ uint32_t gsm[];
    if ((int)blockIdx.x < split)
        gemm_body(A0, lda0, Bt0, bias0, C0, ldc0, K0,
                  blockIdx.y * 128, blockIdx.x * 128, gsm, 1);
    else
        gemm_body(A1, lda1, Bt1, bias1, C1, ldc1, K1,
                  blockIdx.y * 128, (blockIdx.x - split) * 128, gsm, 1);
}

// ================= fused RoPE for q_r (big2) and k_r (big0) =================
__global__ void rope_kernel2(float* __restrict__ b2, float* __restrict__ b0, int n)
{
    int idx = blockIdx.x * blockDim.x + threadIdx.x;
    int which = (idx >= n);
    int id = which ? idx - n : idx;
    if (id >= n) return;
    int i = id & 31;
    int h = (id >> 5) & (NH - 1);
    int t = id >> 9;
    int pos = t & (SS - 1);

    float freq = exp2f(-13.287712379549449f * (float)i / 32.0f);
    float ang = (float)pos * freq;
    float sn, cs;
    sincosf(ang, &sn, &cs);

    float* p = which
        ? b0 + (size_t)t * N0 + KR_OFF0 + h * DRP + 2 * i
        : b2 + (size_t)t * N2 + QR_OFF  + h * DRP + 2 * i;
    float x1 = p[0], x2 = p[1];
    p[0] = roundtf(x1 * cs - x2 * sn);
    p[1] = roundtf(x1 * sn + x2 * cs);
}

// ================= flash attention v5: LDSM S-phase =================
#define ALDQ 204
#define KBUF_WORDS (64 * ALDQ)                        // 13056
#define FL_SMEM ((128 * ALDQ + 2 * KBUF_WORDS) * 4)   // 208,896 B

__global__ __launch_bounds__(256, 1) void flash_mma(
    const float* __restrict__ qcr,
    const float* __restrict__ kvup,
    const float* __restrict__ krb,
    float* __restrict__ out)
{
    extern __shared__ uint32_t sm[];
    uint32_t* Qs = sm;                        // [128][204]
    uint32_t* Kbuf = sm + 128 * ALDQ;         // 2 x [64][204]
    const uint32_t kbase = smem_u32(Kbuf);

    const int tid  = threadIdx.x;
    const int wid  = tid >> 5;
    const int lane = tid & 31;
    const int gr = lane >> 2;
    const int gc = lane & 3;
    const int wq = wid * 16;
    const bool odd = (gc & 1);
    const int l8 = lane & 7;
    const int t4 = lane >> 3;

    const int q0 = blockIdx.x * 128;
    const int h  = blockIdx.y;
    const int b  = blockIdx.z;
    const size_t tok0 = (size_t)b * SS;

    // S-phase B ldmatrix per-lane offsets (within a K buffer), pair p covers j=2p,2p+1
    uint32_t sboff[4];
    #pragma unroll
    for (int p = 0; p < 4; ++p)
        sboff[p] = (uint32_t)(((16*p + 8*(t4 >> 1) + l8) * ALDQ + 4*(t4 & 1)) * 4);

    auto issue_k = [&](int t) {
        const uint32_t kb = kbase + (uint32_t)((t & 1) * KBUF_WORDS) * 4u;
        const int k0tok = t * 64;
        #pragma unroll
        for (int i = 0; i < 8; ++i) {
            int idx = tid + 256 * i;
            int r = idx >> 5, cb = idx & 31;
            CP_ASYNC16(kb + (uint32_t)(r * ALDQ + cb * 4) * 4u,
                       kvup + (tok0 + k0tok + r) * (size_t)DMODEL + h * DHD + cb * 4);
        }
        #pragma unroll
        for (int i = 0; i < 4; ++i) {
            int idx = tid + 256 * i;
            int r = idx >> 4, cb = idx & 15;
            CP_ASYNC16(kb + (uint32_t)(r * ALDQ + 128 + cb * 4) * 4u,
                       krb + (tok0 + k0tok + r) * (size_t)N0 + KR_OFF0 + h * DRP + cb * 4);
        }
    };

    issue_k(0); CP_COMMIT();

    // ---- stage Q tile ----
    for (int idx = tid; idx < 128 * 32; idx += 256) {
        int r = idx >> 5, c4 = (idx & 31) * 4;
        *(uint4*)(Qs + r * ALDQ + c4) =
            *(const uint4*)(qcr + (tok0 + q0 + r) * N2 + h * DHD + c4);
    }
    for (int idx = tid; idx < 128 * 16; idx += 256) {
        int r = idx >> 4, c4 = (idx & 15) * 4;
        *(uint4*)(Qs + r * ALDQ + 128 + c4) =
            *(const uint4*)(qcr + (tok0 + q0 + r) * N2 + QR_OFF + h * DRP + c4);
    }
    __syncthreads();

    // ---- hoist Q fragments into registers via ldmatrix ----
    uint32_t qf[24][4];
    {
        const uint32_t qsu = smem_u32(Qs);
        uint32_t qoff = (uint32_t)(((wq + 8*(t4 & 1) + l8) * ALDQ
                                    + 4*(t4 >> 1)) * 4);
        #pragma unroll
        for (int ks = 0; ks < 24; ++ks)
            LDSM_X4(qf[ks][0], qf[ks][1], qf[ks][2], qf[ks][3],
                    qsu + qoff + (uint32_t)(ks * 32));
    }

    float m0 = -INFINITY, m1 = -INFINITY, l0 = 0.f, l1 = 0.f;
    float o[16][4];
    #pragma unroll
    for (int j = 0; j < 16; ++j)
        #pragma unroll
        for (int c = 0; c < 4; ++c) o[j][c] = 0.f;

    const float scale = 0.08838834764831845f;
    const int srcA = gc >> 1;
    const int srcB = 2 + (gc >> 1);

    for (int kt = 0; kt < SS / 64; ++kt) {
        if (kt + 1 < SS / 64) issue_k(kt + 1);
        CP_COMMIT();
        if (kt + 1 < SS / 64) { CP_WAIT1(); } else { CP_WAIT0(); }
        __syncthreads();

        const uint32_t* Kb = Kbuf + (kt & 1) * KBUF_WORDS;
        const uint32_t kbu = kbase + (uint32_t)((kt & 1) * KBUF_WORDS) * 4u;

        // ---- S = Q @ K^T (B fragments via ldmatrix) ----
        float s[8][4];
        #pragma unroll
        for (int j = 0; j < 8; ++j)
            #pragma unroll
            for (int c = 0; c < 4; ++c) s[j][c] = 0.f;

        #pragma unroll 8
        for (int ks = 0; ks < 24; ++ks) {
            const uint32_t kb4 = (uint32_t)(ks * 32);
            uint32_t bfr[8][2];
            #pragma unroll
            for (int p = 0; p < 4; ++p)
                LDSM_X4(bfr[2*p][0], bfr[2*p][1], bfr[2*p+1][0], bfr[2*p+1][1],
                        kbu + sboff[p] + kb4);
            #pragma unroll
            for (int j = 0; j < 8; ++j)
                MMA_TF32(s[j][0], s[j][1], s[j][2], s[j][3],
                         qf[ks][0], qf[ks][1], qf[ks][2], qf[ks][3],
                         bfr[j][0], bfr[j][1]);
        }

        // ---- online softmax; P stays in s[][] ----
        float mx0 = -INFINITY, mx1 = -INFINITY;
        #pragma unroll
        for (int j = 0; j < 8; ++j) {
            s[j][0] *= scale; s[j][1] *= scale; s[j][2] *= scale; s[j][3] *= scale;
            mx0 = fmaxf(mx0, fmaxf(s[j][0], s[j][1]));
            mx1 = fmaxf(mx1, fmaxf(s[j][2], s[j][3]));
        }
        #pragma unroll
        for (int off = 1; off <= 2; off <<= 1) {
            mx0 = fmaxf(mx0, __shfl_xor_sync(0xffffffffu, mx0, off));
            mx1 = fmaxf(mx1, __shfl_xor_sync(0xffffffffu, mx1, off));
        }
        float m0n = fmaxf(m0, mx0);
        float m1n = fmaxf(m1, mx1);
        float al0 = __expf(m0 - m0n);
        float al1 = __expf(m1 - m1n);
        float rs0 = 0.f, rs1 = 0.f;
        #pragma unroll
        for (int j = 0; j < 8; ++j) {
            s[j][0] = __expf(s[j][0] - m0n);
            s[j][1] = __expf(s[j][1] - m0n);
            s[j][2] = __expf(s[j][2] - m1n);
            s[j][3] = __expf(s[j][3] - m1n);
            rs0 += s[j][0] + s[j][1];
            rs1 += s[j][2] + s[j][3];
        }
        #pragma unroll
        for (int off = 1; off <= 2; off <<= 1) {
            rs0 += __shfl_xor_sync(0xffffffffu, rs0, off);
            rs1 += __shfl_xor_sync(0xffffffffu, rs1, off);
        }
        l0 = l0 * al0 + rs0;
        l1 = l1 * al1 + rs1;
        m0 = m0n; m1 = m1n;
        #pragma unroll
        for (int j = 0; j < 16; ++j) {
            o[j][0] *= al0; o[j][1] *= al0;
            o[j][2] *= al1; o[j][3] *= al1;
        }

        // ---- O += P @ V : A from registers via shuffles; V scalar loads ----
        #pragma unroll 2
        for (int ks = 0; ks < 8; ++ks) {
            const int k0 = ks * 8;
            float v0 = __shfl_sync(0xffffffffu, s[ks][0], srcA, 4);
            float v1 = __shfl_sync(0xffffffffu, s[ks][1], srcA, 4);
            float v2 = __shfl_sync(0xffffffffu, s[ks][2], srcA, 4);
            float v3 = __shfl_sync(0xffffffffu, s[ks][3], srcA, 4);
            float w0 = __shfl_sync(0xffffffffu, s[ks][0], srcB, 4);
            float w1 = __shfl_sync(0xffffffffu, s[ks][1], srcB, 4);
            float w2 = __shfl_sync(0xffffffffu, s[ks][2], srcB, 4);
            float w3 = __shfl_sync(0xffffffffu, s[ks][3], srcB, 4);
            uint32_t a0 = f2tf32(odd ? v1 : v0);
            uint32_t a1 = f2tf32(odd ? v3 : v2);
            uint32_t a2 = f2tf32(odd ? w1 : w0);
            uint32_t a3 = f2tf32(odd ? w3 : w2);
            #pragma unroll
            for (int j = 0; j < 16; ++j) {
                uint32_t b0 = Kb[(k0 + gc) * ALDQ + 8*j + gr];
                uint32_t b1 = Kb[(k0 + gc + 4) * ALDQ + 8*j + gr];
                MMA_TF32(o[j][0], o[j][1], o[j][2], o[j][3], a0, a1, a2, a3, b0, b1);
            }
        }
        __syncthreads();
    }

    float inv0 = 1.0f / l0;
    float inv1 = 1.0f / l1;
    size_t r0 = (tok0 + q0 + wq + gr) * DMODEL + h * DHD;
    size_t r1 = (tok0 + q0 + wq + gr + 8) * DMODEL + h * DHD;
    #pragma unroll
    for (int j = 0; j < 16; ++j) {
        int c = 8*j + 2*gc;
        *(float2*)(out + r0 + c) =
            make_float2(roundtf(o[j][0] * inv0), roundtf(o[j][1] * inv0));
        *(float2*)(out + r1 + c) =
            make_float2(roundtf(o[j][2] * inv1), roundtf(o[j][3] * inv1));
    }
}

// ================= host launch =================
static inline void launch_gemm(const float* A, int lda, const float* Bt,
                               const float* bias, float* C, int ldc,
                               int N, int K, int round_out)
{
    dim3 grid(N / 128, NTOK / 128);
    gemm_cp<<<grid, 256, GEMM_SMEM>>>(A, lda, Bt, bias, C, ldc, K, round_out);
}

extern "C" void kernel_launch(void* const* d_in, const int* in_sizes, int n_in,
                              void* d_out, int out_size)
{
    (void)in_sizes; (void)n_in; (void)out_size;
    const float* x   = (const float*)d_in[0];
    const float* Wd  = (const float*)d_in[1];
    const float* bd  = (const float*)d_in[2];
    const float* Wu  = (const float*)d_in[3];
    const float* bu  = (const float*)d_in[4];
    const float* Wqd = (const float*)d_in[5];
    const float* bqd = (const float*)d_in[6];
    const float* Wqu = (const float*)d_in[7];
    const float* bqu = (const float*)d_in[8];
    const float* Wqr = (const float*)d_in[9];
    const float* bqr = (const float*)d_in[10];
    const float* Wkr = (const float*)d_in[11];
    const float* bkr = (const float*)d_in[12];
    const float* Wo  = (const float*)d_in[13];
    const float* bo  = (const float*)d_in[14];
    float* out = (float*)d_out;

    float *xt, *big0, *kvup, *big2, *attn;
    float *bt0, *wuT, *bt2, *woT, *bias0, *bias2;
    cudaGetSymbolAddress((void**)&xt,    g_xt);
    cudaGetSymbolAddress((void**)&big0,  g_big0);
    cudaGetSymbolAddress((void**)&kvup,  g_kvup);
    cudaGetSymbolAddress((void**)&big2,  g_big2);
    cudaGetSymbolAddress((void**)&attn,  g_attn);
    cudaGetSymbolAddress((void**)&bt0,   g_bt0);
    cudaGetSymbolAddress((void**)&wuT,   g_wuT);
    cudaGetSymbolAddress((void**)&bt2,   g_bt2);
    cudaGetSymbolAddress((void**)&woT,   g_woT);
    cudaGetSymbolAddress((void**)&bias0, g_bias0);
    cudaGetSymbolAddress((void**)&bias2, g_bias2);

    cudaFuncSetAttribute(gemm_cp, cudaFuncAttributeMaxDynamicSharedMemorySize,
                         GEMM_SMEM);
    cudaFuncSetAttribute(gemm_dual, cudaFuncAttributeMaxDynamicSharedMemorySize,
                         GEMM_SMEM);
    cudaFuncSetAttribute(flash_mma, cudaFuncAttributeMaxDynamicSharedMemorySize,
                         FL_SMEM);

    // L0: pre-round x
    round_tf32_kernel<<<(NTOK*DMODEL/4 + 255)/256, 256>>>(x, xt, NTOK*DMODEL/4);
    // L1: fused transpose [Wd|Wqd|Wkr] -> bt0
    transpose_multi<<<dim3(N0/32, DMODEL/32), dim3(32, 8)>>>(
        Wd, DC, Wqd, DCOMP, Wkr, NH*DRP, bt0, DMODEL);
    // L2: bias0
    concat_bias3<<<(N0 + 255)/256, 256>>>(bias0, bd, DC, bqd, DCOMP, bkr, NH*DRP);
    // L3: G1 mega-GEMM  <-- PROFILED
    launch_gemm(xt, DMODEL, bt0, bias0, big0, N0, N0, DMODEL, 1);
    // L4: transpose Wu
    transpose_multi<<<dim3(DMODEL/32, DC/32), dim3(32, 8)>>>(
        Wu, DMODEL, Wu, 0, Wu, 0, wuT, DC);
    // L5: fused transpose [Wqu|Wqr] -> bt2
    transpose_multi<<<dim3(N2/32, DCOMP/32), dim3(32, 8)>>>(
        Wqu, DMODEL, Wqr, NH*DRP, Wqr, 0, bt2, DCOMP);
    // L6: bias2
    concat_bias3<<<(N2 + 255)/256, 256>>>(bias2, bqu, DMODEL, bqr, NH*DRP,
                                          bqr, 0);
    // L7: fused dual GEMM — kv_up + (q_c|q_r)
    {
        dim3 grid(DMODEL/128 + N2/128, NTOK/128);
        gemm_dual<<<grid, 256, GEMM_SMEM>>>(
            big0, N0, wuT, bu, kvup, DMODEL, DC,
            big0 + QCMP_OFF, N0, bt2, bias2, big2, N2, DCOMP,
            DMODEL/128);
    }
    // L8: fused rope
    {
        int n = NTOK * NH * 32;
        rope_kernel2<<<(2*n + 255)/256, 256>>>(big2, big0, n);
    }
    // L9: transpose Wo
    transpose_multi<<<dim3(DMODEL/32, DMODEL/32), dim3(32, 8)>>>(
        Wo, DMODEL, Wo, 0, Wo, 0, woT, DMODEL);
    // L10: attention
    {
        dim3 grid(SS / 128, NH, BB);
        flash_mma<<<grid, 256, FL_SMEM>>>(big2, kvup, big0, attn);
    }
    // L11: output projection
    launch_gemm(attn, DMODEL, woT, bo, out, DMODEL, DMODEL, DMODEL, 0);
}

// round 12
// speedup vs baseline: 1.0869x; 1.0869x over previous
#include <cuda_runtime.h>
#include <math.h>
#include <stdint.h>

#define BB 2
#define SS 2048
#define NH 16
#define DHD 128
#define DRP 64
#define DMODEL 2048
#define DC 512
#define DCOMP 768
#define NTOK (BB*SS)

#define N0 (DC + DCOMP + NH*DRP)     // 2304  (kv_c | q_cmp | k_r)
#define QCMP_OFF DC                  // 512
#define KR_OFF0 (DC + DCOMP)         // 1280
#define N2 (DMODEL + NH*DRP)         // 3072  (q_c | q_r)
#define QR_OFF DMODEL                // 2048

// ---------------- scratch (static device globals; no allocation) ----------------
__device__ float g_xt  [NTOK*DMODEL];
__device__ float g_big0[NTOK*N0];
__device__ float g_kvup[NTOK*DMODEL];
__device__ float g_big2[NTOK*N2];
__device__ float g_attn[NTOK*DMODEL];
__device__ float g_bt0 [N0*DMODEL];
__device__ float g_wuT [DMODEL*DC];
__device__ float g_bt2 [N2*DCOMP];
__device__ float g_woT [DMODEL*DMODEL];
__device__ float g_bias0[N0];
__device__ float g_bias2[N2];

__device__ __forceinline__ uint32_t f2tf32(float x) {
    uint32_t r;
    asm("cvt.rna.tf32.f32 %0, %1;" : "=r"(r) : "f"(x));
    return r;
}
__device__ __forceinline__ float roundtf(float x) {
    return __uint_as_float(f2tf32(x));
}
__device__ __forceinline__ uint32_t smem_u32(const void* p) {
    uint32_t a;
    asm("{ .reg .u64 t; cvta.to.shared.u64 t, %1; cvt.u32.u64 %0, t; }"
        : "=r"(a) : "l"(p));
    return a;
}

#define MMA_TF32(d0,d1,d2,d3, a0,a1,a2,a3, b0,b1) \
    asm volatile( \
        "mma.sync.aligned.m16n8k8.row.col.f32.tf32.tf32.f32 " \
        "{%0,%1,%2,%3}, {%4,%5,%6,%7}, {%8,%9}, {%0,%1,%2,%3};" \
        : "+f"(d0), "+f"(d1), "+f"(d2), "+f"(d3) \
        : "r"(a0), "r"(a1), "r"(a2), "r"(a3), "r"(b0), "r"(b1))

#define LDSM_X4(r0,r1,r2,r3, addr) \
    asm volatile("ldmatrix.sync.aligned.m8n8.x4.shared.b16 {%0,%1,%2,%3}, [%4];" \
        : "=r"(r0), "=r"(r1), "=r"(r2), "=r"(r3) : "r"(addr))

#define CP_ASYNC16(dst, src) \
    asm volatile("cp.async.cg.shared.global [%0], [%1], 16;" \
                 :: "r"(dst), "l"(src))
#define CP_COMMIT() asm volatile("cp.async.commit_group;" ::: "memory")
#define CP_WAIT1()  asm volatile("cp.async.wait_group 1;" ::: "memory")
#define CP_WAIT0()  asm volatile("cp.async.wait_group 0;" ::: "memory")

// ================= helpers =================
__global__ void round_tf32_kernel(const float* __restrict__ in,
                                  float* __restrict__ out, int n4)
{
    int i = blockIdx.x * blockDim.x + threadIdx.x;
    if (i >= n4) return;
    float4 v = ((const float4*)in)[i];
    v.x = roundtf(v.x); v.y = roundtf(v.y);
    v.z = roundtf(v.z); v.w = roundtf(v.w);
    ((float4*)out)[i] = v;
}

__global__ void concat_bias3(float* __restrict__ dst,
                             const float* __restrict__ a, int na,
                             const float* __restrict__ b, int nb,
                             const float* __restrict__ c, int nc)
{
    int i = blockIdx.x * blockDim.x + threadIdx.x;
    if (i < na) dst[i] = a[i];
    else if (i < na + nb) dst[i] = b[i - na];
    else if (i < na + nb + nc) dst[i] = c[i - na - nb];
}

__global__ void transpose_multi(
    const float* __restrict__ in0, int nsz0,
    const float* __restrict__ in1, int nsz1,
    const float* __restrict__ in2, int nsz2,
    float* __restrict__ out, int K)
{
    __shared__ float t[32][33];
    int gn = blockIdx.x * 32;
    int k0 = blockIdx.y * 32;
    const float* src; int N; int col0;
    if (gn < nsz0)              { src = in0; N = nsz0; col0 = gn; }
    else if (gn < nsz0 + nsz1)  { src = in1; N = nsz1; col0 = gn - nsz0; }
    else                        { src = in2; N = nsz2; col0 = gn - nsz0 - nsz1; }
    int tx = threadIdx.x, ty = threadIdx.y;  // (32, 8)
    #pragma unroll
    for (int i = 0; i < 4; ++i)
        t[ty + 8*i][tx] = src[(size_t)(k0 + ty + 8*i) * N + col0 + tx];
    __syncthreads();
    #pragma unroll
    for (int i = 0; i < 4; ++i)
        out[(size_t)(gn + ty + 8*i) * K + k0 + tx] = roundtf(t[tx][ty + 8*i]);
}

// ================= cp.async 3-stage tf32 GEMM body (LDSM fragments) =========
#define GBK 32
#define GSTG 3
#define GLDW 36
#define GSTG_WORDS (256 * GLDW)
#define GEMM_SMEM (GSTG * GSTG_WORDS * 4)    // 110,592 B; x2 CTA

__device__ __forceinline__ void gemm_body(
    const float* __restrict__ A, int lda,
    const float* __restrict__ Bt,
    const float* __restrict__ bias,
    float* __restrict__ C, int ldc,
    int K, int row0, int col0,
    uint32_t* gsm, int round_out)
{
    const int tid  = threadIdx.x;
    const int lane = tid & 31;
    const int wid  = tid >> 5;
    const int wm = wid >> 2, wn = wid & 3;
    const int gr = lane >> 2, gc = lane & 3;
    const int wr = wm * 64,  wc = wn * 32;
    const int l8 = lane & 7;
    const int t4 = lane >> 3;          // ldmatrix tile index 0..3

    const float* Ag = A  + (size_t)row0 * lda;
    const float* Bg = Bt + (size_t)col0 * K;

    const int crow = tid >> 3;
    const int ccol = (tid & 7) * 4;
    const uint32_t smbase = smem_u32(gsm);

    // ldmatrix per-lane byte offsets (within a stage)
    uint32_t aoff[4], boff[2];
    #pragma unroll
    for (int i = 0; i < 4; ++i)
        aoff[i] = (uint32_t)(((wr + 16*i + 8*(t4 & 1) + l8) * GLDW
                              + 4*(t4 >> 1)) * 4);
    #pragma unroll
    for (int p = 0; p < 2; ++p)
        boff[p] = (uint32_t)((128 * GLDW +
                              (wc + 16*p + 8*(t4 >> 1) + l8) * GLDW
                              + 4*(t4 & 1)) * 4);

    const int niter = K / GBK;

    auto issue_stage = [&](int it) {
        const int s = it % GSTG;
        const int ko = it * GBK;
        uint32_t as = smbase + (uint32_t)(s * GSTG_WORDS) * 4u;
        uint32_t bs = as + (uint32_t)(128 * GLDW) * 4u;
        #pragma unroll
        for (int c = 0; c < 4; ++c) {
            int r = crow + 32 * c;
            CP_ASYNC16(as + (uint32_t)(r * GLDW + ccol) * 4u,
                       Ag + (size_t)r * lda + ko + ccol);
            CP_ASYNC16(bs + (uint32_t)(r * GLDW + ccol) * 4u,
                       Bg + (size_t)r * K + ko + ccol);
        }
    };

    float acc[4][4][4];
    #pragma unroll
    for (int i = 0; i < 4; ++i)
        #pragma unroll
        for (int j = 0; j < 4; ++j)
            #pragma unroll
            for (int c = 0; c < 4; ++c) acc[i][j][c] = 0.f;

    issue_stage(0); CP_COMMIT();
    issue_stage(1); CP_COMMIT();

    for (int it = 0; it < niter; ++it) {
        CP_WAIT1();
        __syncthreads();

        if (it + 2 < niter) issue_stage(it + 2);
        CP_COMMIT();

        const uint32_t stg = smbase + (uint32_t)((it % GSTG) * GSTG_WORDS) * 4u;

        #pragma unroll
        for (int ks = 0; ks < 4; ++ks) {
            const uint32_t kb4 = (uint32_t)(ks * 8 * 4);
            uint32_t a[4][4], b[4][2];
            #pragma unroll
            for (int i = 0; i < 4; ++i)
                LDSM_X4(a[i][0], a[i][1], a[i][2], a[i][3], stg + aoff[i] + kb4);
            LDSM_X4(b[0][0], b[0][1], b[1][0], b[1][1], stg + boff[0] + kb4);
            LDSM_X4(b[2][0], b[2][1], b[3][0], b[3][1], stg + boff[1] + kb4);
            #pragma unroll
            for (int i = 0; i < 4; ++i)
                #pragma unroll
                for (int j = 0; j < 4; ++j)
                    MMA_TF32(acc[i][j][0], acc[i][j][1], acc[i][j][2], acc[i][j][3],
                             a[i][0], a[i][1], a[i][2], a[i][3], b[j][0], b[j][1]);
        }
    }

    #pragma unroll
    for (int j = 0; j < 4; ++j) {
        int c = col0 + wc + 8*j + 2*gc;
        float bv0 = bias[c], bv1 = bias[c + 1];
        #pragma unroll
        for (int i = 0; i < 4; ++i) {
            int r = row0 + wr + 16*i + gr;
            float f0 = acc[i][j][0] + bv0, f1 = acc[i][j][1] + bv1;
            float f2 = acc[i][j][2] + bv0, f3 = acc[i][j][3] + bv1;
            if (round_out) {
                f0 = roundtf(f0); f1 = roundtf(f1);
                f2 = roundtf(f2); f3 = roundtf(f3);
            }
            *(float2*)(C + (size_t)r * ldc + c)       = make_float2(f0, f1);
            *(float2*)(C + (size_t)(r + 8) * ldc + c) = make_float2(f2, f3);
        }
    }
}

__global__ __launch_bounds__(256, 2) void gemm_cp(
    const float* __restrict__ A, int lda,
    const float* __restrict__ Bt,
    const float* __restrict__ bias,
    float* __restrict__ C, int ldc,
    int K, int round_out)
{
    extern __shared__ uint32_t gsm[];
    gemm_body(A, lda, Bt, bias, C, ldc, K,
              blockIdx.y * 128, blockIdx.x * 128, gsm, round_out);
}

__global__ __launch_bounds__(256, 2) void gemm_dual(
    const float* __restrict__ A0, int lda0, const float* __restrict__ Bt0,
    const float* __restrict__ bias0, float* __restrict__ C0, int ldc0, int K0,
    const float* __restrict__ A1, int lda1, const float* __restrict__ Bt1,
    const float* __restrict__ bias1, float* __restrict__ C1, int ldc1, int K1,
    int split)
{
    extern __shared__ uint32_t gsm[];
    if ((int)blockIdx.x < split)
        gemm_body(A0, lda0, Bt0, bias0, C0, ldc0, K0,
                  blockIdx.y * 128, blockIdx.x * 128, gsm, 1);
    else
        gemm_body(A1, lda1, Bt1, bias1, C1, ldc1, K1,
                  blockIdx.y * 128, (blockIdx.x - split) * 128, gsm, 1);
}

// ================= fused RoPE for q_r (big2) and k_r (big0) =================
__global__ void rope_kernel2(float* __restrict__ b2, float* __restrict__ b0, int n)
{
    int idx = blockIdx.x * blockDim.x + threadIdx.x;
    int which = (idx >= n);
    int id = which ? idx - n : idx;
    if (id >= n) return;
    int i = id & 31;
    int h = (id >> 5) & (NH - 1);
    int t = id >> 9;
    int pos = t & (SS - 1);

    float freq = exp2f(-13.287712379549449f * (float)i / 32.0f);
    float ang = (float)pos * freq;
    float sn, cs;
    sincosf(ang, &sn, &cs);

    float* p = which
        ? b0 + (size_t)t * N0 + KR_OFF0 + h * DRP + 2 * i
        : b2 + (size_t)t * N2 + QR_OFF  + h * DRP + 2 * i;
    float x1 = p[0], x2 = p[1];
    p[0] = roundtf(x1 * cs - x2 * sn);
    p[1] = roundtf(x1 * sn + x2 * cs);
}

// ================= flash attention (round-10 version: best measured) =========
// ALDQ=200 (conflict-free PV loads); Q fragments held in registers.
#define ALDQ 200
#define KBUF_WORDS (64 * ALDQ)                        // 12800
#define FL_SMEM ((128 * ALDQ + 2 * KBUF_WORDS) * 4)   // 204,800 B

__global__ __launch_bounds__(256, 1) void flash_mma(
    const float* __restrict__ qcr,    // big2: q_c cols [0,2048), q_r at QR_OFF; ld N2
    const float* __restrict__ kvup,   // [4096][2048]
    const float* __restrict__ krb,    // big0: k_r at KR_OFF0; ld N0
    float* __restrict__ out)
{
    extern __shared__ uint32_t sm[];
    uint32_t* Qs = sm;                        // [128][200]
    uint32_t* Kbuf = sm + 128 * ALDQ;         // 2 x [64][200]
    const uint32_t kbase = smem_u32(Kbuf);

    const int tid  = threadIdx.x;
    const int wid  = tid >> 5;
    const int lane = tid & 31;
    const int gr = lane >> 2;
    const int gc = lane & 3;
    const int wq = wid * 16;
    const bool odd = (gc & 1);

    const int q0 = blockIdx.x * 128;
    const int h  = blockIdx.y;
    const int b  = blockIdx.z;
    const size_t tok0 = (size_t)b * SS;

    auto issue_k = [&](int t) {
        const uint32_t kb = kbase + (uint32_t)((t & 1) * KBUF_WORDS) * 4u;
        const int k0tok = t * 64;
        #pragma unroll
        for (int i = 0; i < 8; ++i) {            // kvup cols: 64 rows x 32 chunks
            int idx = tid + 256 * i;
            int r = idx >> 5, cb = idx & 31;
            CP_ASYNC16(kb + (uint32_t)(r * ALDQ + cb * 4) * 4u,
                       kvup + (tok0 + k0tok + r) * (size_t)DMODEL + h * DHD + cb * 4);
        }
        #pragma unroll
        for (int i = 0; i < 4; ++i) {            // k_r cols: 64 rows x 16 chunks
            int idx = tid + 256 * i;
            int r = idx >> 4, cb = idx & 15;
            CP_ASYNC16(kb + (uint32_t)(r * ALDQ + 128 + cb * 4) * 4u,
                       krb + (tok0 + k0tok + r) * (size_t)N0 + KR_OFF0 + h * DRP + cb * 4);
        }
    };

    issue_k(0); CP_COMMIT();

    // ---- stage Q tile ----
    for (int idx = tid; idx < 128 * 32; idx += 256) {
        int r = idx >> 5, c4 = (idx & 31) * 4;
        *(uint4*)(Qs + r * ALDQ + c4) =
            *(const uint4*)(qcr + (tok0 + q0 + r) * N2 + h * DHD + c4);
    }
    for (int idx = tid; idx < 128 * 16; idx += 256) {
        int r = idx >> 4, c4 = (idx & 15) * 4;
        *(uint4*)(Qs + r * ALDQ + 128 + c4) =
            *(const uint4*)(qcr + (tok0 + q0 + r) * N2 + QR_OFF + h * DRP + c4);
    }
    __syncthreads();

    // ---- hoist Q fragments into registers (loop-invariant across key tiles) ----
    uint32_t qf[24][4];
    #pragma unroll
    for (int ks = 0; ks < 24; ++ks) {
        const uint32_t* abase = Qs + (wq + gr) * ALDQ + ks * 8 + gc;
        qf[ks][0] = abase[0];
        qf[ks][2] = abase[4];
        qf[ks][1] = abase[8 * ALDQ];
        qf[ks][3] = abase[8 * ALDQ + 4];
    }

    float m0 = -INFINITY, m1 = -INFINITY, l0 = 0.f, l1 = 0.f;
    float o[16][4];
    #pragma unroll
    for (int j = 0; j < 16; ++j)
        #pragma unroll
        for (int c = 0; c < 4; ++c) o[j][c] = 0.f;

    const float scale = 0.08838834764831845f;  // 1/sqrt(128)
    const int srcA = gc >> 1;
    const int srcB = 2 + (gc >> 1);

    for (int kt = 0; kt < SS / 64; ++kt) {
        if (kt + 1 < SS / 64) issue_k(kt + 1);
        CP_COMMIT();
        if (kt + 1 < SS / 64) { CP_WAIT1(); } else { CP_WAIT0(); }
        __syncthreads();

        const uint32_t* Kb = Kbuf + (kt & 1) * KBUF_WORDS;

        // ---- S = Q @ K^T ----
        float s[8][4];
        #pragma unroll
        for (int j = 0; j < 8; ++j)
            #pragma unroll
            for (int c = 0; c < 4; ++c) s[j][c] = 0.f;

        #pragma unroll
        for (int ks = 0; ks < 24; ++ks) {
            const int k0 = ks * 8;
            #pragma unroll
            for (int j = 0; j < 8; ++j) {
                const uint32_t* bbase = Kb + (8*j + gr) * ALDQ + k0 + gc;
                uint32_t b0 = bbase[0];
                uint32_t b1 = bbase[4];
                MMA_TF32(s[j][0], s[j][1], s[j][2], s[j][3],
                         qf[ks][0], qf[ks][1], qf[ks][2], qf[ks][3], b0, b1);
            }
        }

        // ---- online softmax; P stays in s[][] ----
        float mx0 = -INFINITY, mx1 = -INFINITY;
        #pragma unroll
        for (int j = 0; j < 8; ++j) {
            s[j][0] *= scale; s[j][1] *= scale; s[j][2] *= scale; s[j][3] *= scale;
            mx0 = fmaxf(mx0, fmaxf(s[j][0], s[j][1]));
            mx1 = fmaxf(mx1, fmaxf(s[j][2], s[j][3]));
        }
        #pragma unroll
        for (int off = 1; off <= 2; off <<= 1) {
            mx0 = fmaxf(mx0, __shfl_xor_sync(0xffffffffu, mx0, off));
            mx1 = fmaxf(mx1, __shfl_xor_sync(0xffffffffu, mx1, off));
        }
        float m0n = fmaxf(m0, mx0);
        float m1n = fmaxf(m1, mx1);
        float al0 = __expf(m0 - m0n);
        float al1 = __expf(m1 - m1n);
        float rs0 = 0.f, rs1 = 0.f;
        #pragma unroll
        for (int j = 0; j < 8; ++j) {
            s[j][0] = __expf(s[j][0] - m0n);
            s[j][1] = __expf(s[j][1] - m0n);
            s[j][2] = __expf(s[j][2] - m1n);
            s[j][3] = __expf(s[j][3] - m1n);
            rs0 += s[j][0] + s[j][1];
            rs1 += s[j][2] + s[j][3];
        }
        #pragma unroll
        for (int off = 1; off <= 2; off <<= 1) {
            rs0 += __shfl_xor_sync(0xffffffffu, rs0, off);
            rs1 += __shfl_xor_sync(0xffffffffu, rs1, off);
        }
        l0 = l0 * al0 + rs0;
        l1 = l1 * al1 + rs1;
        m0 = m0n; m1 = m1n;
        #pragma unroll
        for (int j = 0; j < 16; ++j) {
            o[j][0] *= al0; o[j][1] *= al0;
            o[j][2] *= al1; o[j][3] *= al1;
        }

        // ---- O += P @ V : A-fragments from registers via width-4 shuffles ----
        #pragma unroll 2
        for (int ks = 0; ks < 8; ++ks) {
            const int k0 = ks * 8;
            float v0 = __shfl_sync(0xffffffffu, s[ks][0], srcA, 4);
            float v1 = __shfl_sync(0xffffffffu, s[ks][1], srcA, 4);
            float v2 = __shfl_sync(0xffffffffu, s[ks][2], srcA, 4);
            float v3 = __shfl_sync(0xffffffffu, s[ks][3], srcA, 4);
            float w0 = __shfl_sync(0xffffffffu, s[ks][0], srcB, 4);
            float w1 = __shfl_sync(0xffffffffu, s[ks][1], srcB, 4);
            float w2 = __shfl_sync(0xffffffffu, s[ks][2], srcB, 4);
            float w3 = __shfl_sync(0xffffffffu, s[ks][3], srcB, 4);
            uint32_t a0 = f2tf32(odd ? v1 : v0);
            uint32_t a1 = f2tf32(odd ? v3 : v2);
            uint32_t a2 = f2tf32(odd ? w1 : w0);
            uint32_t a3 = f2tf32(odd ? w3 : w2);
            #pragma unroll
            for (int j = 0; j < 16; ++j) {
                uint32_t b0 = Kb[(k0 + gc) * ALDQ + 8*j + gr];
                uint32_t b1 = Kb[(k0 + gc + 4) * ALDQ + 8*j + gr];
                MMA_TF32(o[j][0], o[j][1], o[j][2], o[j][3], a0, a1, a2, a3, b0, b1);
            }
        }
        __syncthreads();   // all warps done with Kbuf[kt&1] before reissue
    }

    // ---- epilogue (write tf32-rounded attn for the Wo GEMM) ----
    float inv0 = 1.0f / l0;
    float inv1 = 1.0f / l1;
    size_t r0 = (tok0 + q0 + wq + gr) * DMODEL + h * DHD;
    size_t r1 = (tok0 + q0 + wq + gr + 8) * DMODEL + h * DHD;
    #pragma unroll
    for (int j = 0; j < 16; ++j) {
        int c = 8*j + 2*gc;
        *(float2*)(out + r0 + c) =
            make_float2(roundtf(o[j][0] * inv0), roundtf(o[j][1] * inv0));
        *(float2*)(out + r1 + c) =
            make_float2(roundtf(o[j][2] * inv1), roundtf(o[j][3] * inv1));
    }
}

// ================= host launch =================
static inline void launch_gemm(const float* A, int lda, const float* Bt,
                               const float* bias, float* C, int ldc,
                               int N, int K, int round_out)
{
    dim3 grid(N / 128, NTOK / 128);
    gemm_cp<<<grid, 256, GEMM_SMEM>>>(A, lda, Bt, bias, C, ldc, K, round_out);
}

extern "C" void kernel_launch(void* const* d_in, const int* in_sizes, int n_in,
                              void* d_out, int out_size)
{
    (void)in_sizes; (void)n_in; (void)out_size;
    const float* x   = (const float*)d_in[0];
    const float* Wd  = (const float*)d_in[1];
    const float* bd  = (const float*)d_in[2];
    const float* Wu  = (const float*)d_in[3];
    const float* bu  = (const float*)d_in[4];
    const float* Wqd = (const float*)d_in[5];
    const float* bqd = (const float*)d_in[6];
    const float* Wqu = (const float*)d_in[7];
    const float* bqu = (const float*)d_in[8];
    const float* Wqr = (const float*)d_in[9];
    const float* bqr = (const float*)d_in[10];
    const float* Wkr = (const float*)d_in[11];
    const float* bkr = (const float*)d_in[12];
    const float* Wo  = (const float*)d_in[13];
    const float* bo  = (const float*)d_in[14];
    float* out = (float*)d_out;

    float *xt, *big0, *kvup, *big2, *attn;
    float *bt0, *wuT, *bt2, *woT, *bias0, *bias2;
    cudaGetSymbolAddress((void**)&xt,    g_xt);
    cudaGetSymbolAddress((void**)&big0,  g_big0);
    cudaGetSymbolAddress((void**)&kvup,  g_kvup);
    cudaGetSymbolAddress((void**)&big2,  g_big2);
    cudaGetSymbolAddress((void**)&attn,  g_attn);
    cudaGetSymbolAddress((void**)&bt0,   g_bt0);
    cudaGetSymbolAddress((void**)&wuT,   g_wuT);
    cudaGetSymbolAddress((void**)&bt2,   g_bt2);
    cudaGetSymbolAddress((void**)&woT,   g_woT);
    cudaGetSymbolAddress((void**)&bias0, g_bias0);
    cudaGetSymbolAddress((void**)&bias2, g_bias2);

    cudaFuncSetAttribute(gemm_cp, cudaFuncAttributeMaxDynamicSharedMemorySize,
                         GEMM_SMEM);
    cudaFuncSetAttribute(gemm_dual, cudaFuncAttributeMaxDynamicSharedMemorySize,
                         GEMM_SMEM);
    cudaFuncSetAttribute(flash_mma, cudaFuncAttributeMaxDynamicSharedMemorySize,
                         FL_SMEM);

    // L0: pre-round x
    round_tf32_kernel<<<(NTOK*DMODEL/4 + 255)/256, 256>>>(x, xt, NTOK*DMODEL/4);
    // L1: fused transpose [Wd|Wqd|Wkr] -> bt0
    transpose_multi<<<dim3(N0/32, DMODEL/32), dim3(32, 8)>>>(
        Wd, DC, Wqd, DCOMP, Wkr, NH*DRP, bt0, DMODEL);
    // L2: bias0
    concat_bias3<<<(N0 + 255)/256, 256>>>(bias0, bd, DC, bqd, DCOMP, bkr, NH*DRP);
    // L3: G1 mega-GEMM  <-- PROFILED
    launch_gemm(xt, DMODEL, bt0, bias0, big0, N0, N0, DMODEL, 1);
    // L4: transpose Wu
    transpose_multi<<<dim3(DMODEL/32, DC/32), dim3(32, 8)>>>(
        Wu, DMODEL, Wu, 0, Wu, 0, wuT, DC);
    // L5: fused transpose [Wqu|Wqr] -> bt2
    transpose_multi<<<dim3(N2/32, DCOMP/32), dim3(32, 8)>>>(
        Wqu, DMODEL, Wqr, NH*DRP, Wqr, 0, bt2, DCOMP);
    // L6: bias2
    concat_bias3<<<(N2 + 255)/256, 256>>>(bias2, bqu, DMODEL, bqr, NH*DRP,
                                          bqr, 0);
    // L7: fused dual GEMM — kv_up + (q_c|q_r)
    {
        dim3 grid(DMODEL/128 + N2/128, NTOK/128);
        gemm_dual<<<grid, 256, GEMM_SMEM>>>(
            big0, N0, wuT, bu, kvup, DMODEL, DC,
            big0 + QCMP_OFF, N0, bt2, bias2, big2, N2, DCOMP,
            DMODEL/128);
    }
    // L8: fused rope
    {
        int n = NTOK * NH * 32;
        rope_kernel2<<<(2*n + 255)/256, 256>>>(big2, big0, n);
    }
    // L9: transpose Wo
    transpose_multi<<<dim3(DMODEL/32, DMODEL/32), dim3(32, 8)>>>(
        Wo, DMODEL, Wo, 0, Wo, 0, woT, DMODEL);
    // L10: attention
    {
        dim3 grid(SS / 128, NH, BB);
        flash_mma<<<grid, 256, FL_SMEM>>>(big2, kvup, big0, attn);
    }
    // L11: output projection
    launch_gemm(attn, DMODEL, woT, bo, out, DMODEL, DMODEL, DMODEL, 0);
}

// round 13
// speedup vs baseline: 1.1016x; 1.0135x over previous
#include <cuda_runtime.h>
#include <math.h>
#include <stdint.h>

#define BB 2
#define SS 2048
#define NH 16
#define DHD 128
#define DRP 64
#define DMODEL 2048
#define DC 512
#define DCOMP 768
#define NTOK (BB*SS)

#define N0 (DC + DCOMP + NH*DRP)     // 2304  (kv_c | q_cmp | k_r)
#define QCMP_OFF DC                  // 512
#define KR_OFF0 (DC + DCOMP)         // 1280
#define N2 (DMODEL + NH*DRP)         // 3072  (q_c | q_r)
#define QR_OFF DMODEL                // 2048

// ---------------- scratch (static device globals; no allocation) ----------------
__device__ float g_xt  [NTOK*DMODEL];
__device__ float g_big0[NTOK*N0];
__device__ float g_kvup[NTOK*DMODEL];
__device__ float g_big2[NTOK*N2];
__device__ float g_attn[NTOK*DMODEL];
__device__ float g_bt0 [N0*DMODEL];
__device__ float g_wuT [DMODEL*DC];
__device__ float g_bt2 [N2*DCOMP];
__device__ float g_woT [DMODEL*DMODEL];
__device__ float g_bias0[N0];
__device__ float g_bias2[N2];

__device__ __forceinline__ uint32_t f2tf32(float x) {
    uint32_t r;
    asm("cvt.rna.tf32.f32 %0, %1;" : "=r"(r) : "f"(x));
    return r;
}
__device__ __forceinline__ float roundtf(float x) {
    return __uint_as_float(f2tf32(x));
}
__device__ __forceinline__ uint32_t smem_u32(const void* p) {
    uint32_t a;
    asm("{ .reg .u64 t; cvta.to.shared.u64 t, %1; cvt.u32.u64 %0, t; }"
        : "=r"(a) : "l"(p));
    return a;
}

#define MMA_TF32(d0,d1,d2,d3, a0,a1,a2,a3, b0,b1) \
    asm volatile( \
        "mma.sync.aligned.m16n8k8.row.col.f32.tf32.tf32.f32 " \
        "{%0,%1,%2,%3}, {%4,%5,%6,%7}, {%8,%9}, {%0,%1,%2,%3};" \
        : "+f"(d0), "+f"(d1), "+f"(d2), "+f"(d3) \
        : "r"(a0), "r"(a1), "r"(a2), "r"(a3), "r"(b0), "r"(b1))

#define LDSM_X4(r0,r1,r2,r3, addr) \
    asm volatile("ldmatrix.sync.aligned.m8n8.x4.shared.b16 {%0,%1,%2,%3}, [%4];" \
        : "=r"(r0), "=r"(r1), "=r"(r2), "=r"(r3) : "r"(addr))

#define CP_ASYNC16(dst, src) \
    asm volatile("cp.async.cg.shared.global [%0], [%1], 16;" \
                 :: "r"(dst), "l"(src))
#define CP_COMMIT() asm volatile("cp.async.commit_group;" ::: "memory")
#define CP_WAIT1()  asm volatile("cp.async.wait_group 1;" ::: "memory")

// ================= helpers =================
__global__ void round_tf32_kernel(const float* __restrict__ in,
                                  float* __restrict__ out, int n4)
{
    int i = blockIdx.x * blockDim.x + threadIdx.x;
    if (i >= n4) return;
    float4 v = ((const float4*)in)[i];
    v.x = roundtf(v.x); v.y = roundtf(v.y);
    v.z = roundtf(v.z); v.w = roundtf(v.w);
    ((float4*)out)[i] = v;
}

__global__ void concat_bias3(float* __restrict__ dst,
                             const float* __restrict__ a, int na,
                             const float* __restrict__ b, int nb,
                             const float* __restrict__ c, int nc)
{
    int i = blockIdx.x * blockDim.x + threadIdx.x;
    if (i < na) dst[i] = a[i];
    else if (i < na + nb) dst[i] = b[i - na];
    else if (i < na + nb + nc) dst[i] = c[i - na - nb];
}

__global__ void transpose_multi(
    const float* __restrict__ in0, int nsz0,
    const float* __restrict__ in1, int nsz1,
    const float* __restrict__ in2, int nsz2,
    float* __restrict__ out, int K)
{
    __shared__ float t[32][33];
    int gn = blockIdx.x * 32;
    int k0 = blockIdx.y * 32;
    const float* src; int N; int col0;
    if (gn < nsz0)              { src = in0; N = nsz0; col0 = gn; }
    else if (gn < nsz0 + nsz1)  { src = in1; N = nsz1; col0 = gn - nsz0; }
    else                        { src = in2; N = nsz2; col0 = gn - nsz0 - nsz1; }
    int tx = threadIdx.x, ty = threadIdx.y;  // (32, 8)
    #pragma unroll
    for (int i = 0; i < 4; ++i)
        t[ty + 8*i][tx] = src[(size_t)(k0 + ty + 8*i) * N + col0 + tx];
    __syncthreads();
    #pragma unroll
    for (int i = 0; i < 4; ++i)
        out[(size_t)(gn + ty + 8*i) * K + k0 + tx] = roundtf(t[tx][ty + 8*i]);
}

// ================= cp.async 3-stage tf32 GEMM body (LDSM fragments) =========
#define GBK 32
#define GSTG 3
#define GLDW 36
#define GSTG_WORDS (256 * GLDW)
#define GEMM_SMEM (GSTG * GSTG_WORDS * 4)    // 110,592 B; x2 CTA

__device__ __forceinline__ void gemm_body(
    const float* __restrict__ A, int lda,
    const float* __restrict__ Bt,
    const float* __restrict__ bias,
    float* __restrict__ C, int ldc,
    int K, int row0, int col0,
    uint32_t* gsm, int round_out)
{
    const int tid  = threadIdx.x;
    const int lane = tid & 31;
    const int wid  = tid >> 5;
    const int wm = wid >> 2, wn = wid & 3;
    const int gr = lane >> 2, gc = lane & 3;
    const int wr = wm * 64,  wc = wn * 32;
    const int l8 = lane & 7;
    const int t4 = lane >> 3;          // ldmatrix tile index 0..3

    const float* Ag = A  + (size_t)row0 * lda;
    const float* Bg = Bt + (size_t)col0 * K;

    const int crow = tid >> 3;
    const int ccol = (tid & 7) * 4;
    const uint32_t smbase = smem_u32(gsm);

    uint32_t aoff[4], boff[2];
    #pragma unroll
    for (int i = 0; i < 4; ++i)
        aoff[i] = (uint32_t)(((wr + 16*i + 8*(t4 & 1) + l8) * GLDW
                              + 4*(t4 >> 1)) * 4);
    #pragma unroll
    for (int p = 0; p < 2; ++p)
        boff[p] = (uint32_t)((128 * GLDW +
                              (wc + 16*p + 8*(t4 >> 1) + l8) * GLDW
                              + 4*(t4 & 1)) * 4);

    const int niter = K / GBK;

    auto issue_stage = [&](int it) {
        const int s = it % GSTG;
        const int ko = it * GBK;
        uint32_t as = smbase + (uint32_t)(s * GSTG_WORDS) * 4u;
        uint32_t bs = as + (uint32_t)(128 * GLDW) * 4u;
        #pragma unroll
        for (int c = 0; c < 4; ++c) {
            int r = crow + 32 * c;
            CP_ASYNC16(as + (uint32_t)(r * GLDW + ccol) * 4u,
                       Ag + (size_t)r * lda + ko + ccol);
            CP_ASYNC16(bs + (uint32_t)(r * GLDW + ccol) * 4u,
                       Bg + (size_t)r * K + ko + ccol);
        }
    };

    float acc[4][4][4];
    #pragma unroll
    for (int i = 0; i < 4; ++i)
        #pragma unroll
        for (int j = 0; j < 4; ++j)
            #pragma unroll
            for (int c = 0; c < 4; ++c) acc[i][j][c] = 0.f;

    issue_stage(0); CP_COMMIT();
    issue_stage(1); CP_COMMIT();

    for (int it = 0; it < niter; ++it) {
        CP_WAIT1();
        __syncthreads();

        if (it + 2 < niter) issue_stage(it + 2);
        CP_COMMIT();

        const uint32_t stg = smbase + (uint32_t)((it % GSTG) * GSTG_WORDS) * 4u;

        #pragma unroll
        for (int ks = 0; ks < 4; ++ks) {
            const uint32_t kb4 = (uint32_t)(ks * 8 * 4);
            uint32_t a[4][4], b[4][2];
            #pragma unroll
            for (int i = 0; i < 4; ++i)
                LDSM_X4(a[i][0], a[i][1], a[i][2], a[i][3], stg + aoff[i] + kb4);
            LDSM_X4(b[0][0], b[0][1], b[1][0], b[1][1], stg + boff[0] + kb4);
            LDSM_X4(b[2][0], b[2][1], b[3][0], b[3][1], stg + boff[1] + kb4);
            #pragma unroll
            for (int i = 0; i < 4; ++i)
                #pragma unroll
                for (int j = 0; j < 4; ++j)
                    MMA_TF32(acc[i][j][0], acc[i][j][1], acc[i][j][2], acc[i][j][3],
                             a[i][0], a[i][1], a[i][2], a[i][3], b[j][0], b[j][1]);
        }
    }

    #pragma unroll
    for (int j = 0; j < 4; ++j) {
        int c = col0 + wc + 8*j + 2*gc;
        float bv0 = bias[c], bv1 = bias[c + 1];
        #pragma unroll
        for (int i = 0; i < 4; ++i) {
            int r = row0 + wr + 16*i + gr;
            float f0 = acc[i][j][0] + bv0, f1 = acc[i][j][1] + bv1;
            float f2 = acc[i][j][2] + bv0, f3 = acc[i][j][3] + bv1;
            if (round_out) {
                f0 = roundtf(f0); f1 = roundtf(f1);
                f2 = roundtf(f2); f3 = roundtf(f3);
            }
            *(float2*)(C + (size_t)r * ldc + c)       = make_float2(f0, f1);
            *(float2*)(C + (size_t)(r + 8) * ldc + c) = make_float2(f2, f3);
        }
    }
}

__global__ __launch_bounds__(256, 2) void gemm_cp(
    const float* __restrict__ A, int lda,
    const float* __restrict__ Bt,
    const float* __restrict__ bias,
    float* __restrict__ C, int ldc,
    int K, int round_out)
{
    extern __shared__ uint32_t gsm[];
    gemm_body(A, lda, Bt, bias, C, ldc, K,
              blockIdx.y * 128, blockIdx.x * 128, gsm, round_out);
}

__global__ __launch_bounds__(256, 2) void gemm_dual(
    const float* __restrict__ A0, int lda0, const float* __restrict__ Bt0,
    const float* __restrict__ bias0, float* __restrict__ C0, int ldc0, int K0,
    const float* __restrict__ A1, int lda1, const float* __restrict__ Bt1,
    const float* __restrict__ bias1, float* __restrict__ C1, int ldc1, int K1,
    int split)
{
    extern __shared__ uint32_t gsm[];
    if ((int)blockIdx.x < split)
        gemm_body(A0, lda0, Bt0, bias0, C0, ldc0, K0,
                  blockIdx.y * 128, blockIdx.x * 128, gsm, 1);
    else
        gemm_body(A1, lda1, Bt1, bias1, C1, ldc1, K1,
                  blockIdx.y * 128, (blockIdx.x - split) * 128, gsm, 1);
}

// ================= fused RoPE for q_r (big2) and k_r (big0) =================
__global__ void rope_kernel2(float* __restrict__ b2, float* __restrict__ b0, int n)
{
    int idx = blockIdx.x * blockDim.x + threadIdx.x;
    int which = (idx >= n);
    int id = which ? idx - n : idx;
    if (id >= n) return;
    int i = id & 31;
    int h = (id >> 5) & (NH - 1);
    int t = id >> 9;
    int pos = t & (SS - 1);

    float freq = exp2f(-13.287712379549449f * (float)i / 32.0f);
    float ang = (float)pos * freq;
    float sn, cs;
    sincosf(ang, &sn, &cs);

    float* p = which
        ? b0 + (size_t)t * N0 + KR_OFF0 + h * DRP + 2 * i
        : b2 + (size_t)t * N2 + QR_OFF  + h * DRP + 2 * i;
    float x1 = p[0], x2 = p[1];
    p[0] = roundtf(x1 * cs - x2 * sn);
    p[1] = roundtf(x1 * sn + x2 * cs);
}

// ================= flash attention v6: 3-way K ring, ONE barrier per tile ====
// Q staged temporarily in K buffers 1&2 (exactly 2*KBUF words), hoisted to regs,
// then all 3 buffers cycle as the K ring. ALDQ=200 keeps PV loads conflict-free.
#define ALDQ 200
#define KBUF_WORDS (64 * ALDQ)                 // 12800 words = 51,200 B
#define FL_SMEM (3 * KBUF_WORDS * 4)           // 153,600 B

__global__ __launch_bounds__(256, 1) void flash_mma(
    const float* __restrict__ qcr,    // big2: q_c cols [0,2048), q_r at QR_OFF; ld N2
    const float* __restrict__ kvup,   // [4096][2048]
    const float* __restrict__ krb,    // big0: k_r at KR_OFF0; ld N0
    float* __restrict__ out)
{
    extern __shared__ uint32_t sm[];
    uint32_t* Kbuf = sm;                       // 3 x [64][200]
    uint32_t* Qs = sm + KBUF_WORDS;            // temp Q staging: [128][200]
    const uint32_t kbase = smem_u32(Kbuf);

    const int tid  = threadIdx.x;
    const int wid  = tid >> 5;
    const int lane = tid & 31;
    const int gr = lane >> 2;
    const int gc = lane & 3;
    const int wq = wid * 16;
    const bool odd = (gc & 1);

    const int q0 = blockIdx.x * 128;
    const int h  = blockIdx.y;
    const int b  = blockIdx.z;
    const size_t tok0 = (size_t)b * SS;

    auto issue_k = [&](int t) {
        const uint32_t kb = kbase + (uint32_t)((t % 3) * KBUF_WORDS) * 4u;
        const int k0tok = t * 64;
        #pragma unroll
        for (int i = 0; i < 8; ++i) {            // kvup cols: 64 rows x 32 chunks
            int idx = tid + 256 * i;
            int r = idx >> 5, cb = idx & 31;
            CP_ASYNC16(kb + (uint32_t)(r * ALDQ + cb * 4) * 4u,
                       kvup + (tok0 + k0tok + r) * (size_t)DMODEL + h * DHD + cb * 4);
        }
        #pragma unroll
        for (int i = 0; i < 4; ++i) {            // k_r cols: 64 rows x 16 chunks
            int idx = tid + 256 * i;
            int r = idx >> 4, cb = idx & 15;
            CP_ASYNC16(kb + (uint32_t)(r * ALDQ + 128 + cb * 4) * 4u,
                       krb + (tok0 + k0tok + r) * (size_t)N0 + KR_OFF0 + h * DRP + cb * 4);
        }
    };

    // prefetch K tile 0 into buf0 while Q stages into bufs 1-2
    issue_k(0); CP_COMMIT();

    // ---- stage Q tile (coalesced) into Qs (= bufs 1&2 region) ----
    for (int idx = tid; idx < 128 * 32; idx += 256) {
        int r = idx >> 5, c4 = (idx & 31) * 4;
        *(uint4*)(Qs + r * ALDQ + c4) =
            *(const uint4*)(qcr + (tok0 + q0 + r) * N2 + h * DHD + c4);
    }
    for (int idx = tid; idx < 128 * 16; idx += 256) {
        int r = idx >> 4, c4 = (idx & 15) * 4;
        *(uint4*)(Qs + r * ALDQ + 128 + c4) =
            *(const uint4*)(qcr + (tok0 + q0 + r) * N2 + QR_OFF + h * DRP + c4);
    }
    __syncthreads();

    // ---- hoist Q fragments into registers ----
    uint32_t qf[24][4];
    #pragma unroll
    for (int ks = 0; ks < 24; ++ks) {
        const uint32_t* abase = Qs + (wq + gr) * ALDQ + ks * 8 + gc;
        qf[ks][0] = abase[0];
        qf[ks][2] = abase[4];
        qf[ks][1] = abase[8 * ALDQ];
        qf[ks][3] = abase[8 * ALDQ + 4];
    }
    __syncthreads();   // all warps hoisted; bufs 1-2 may now be overwritten

    // start the K ring: issue tile 1 (buf1)
    issue_k(1); CP_COMMIT();

    float m0 = -INFINITY, m1 = -INFINITY, l0 = 0.f, l1 = 0.f;
    float o[16][4];
    #pragma unroll
    for (int j = 0; j < 16; ++j)
        #pragma unroll
        for (int c = 0; c < 4; ++c) o[j][c] = 0.f;

    const float scale = 0.08838834764831845f;  // 1/sqrt(128)
    const int srcA = gc >> 1;
    const int srcB = 2 + (gc >> 1);

    for (int kt = 0; kt < SS / 64; ++kt) {
        CP_WAIT1();          // tile kt landed (kt+1 may still be in flight)
        __syncthreads();     // single barrier: everyone done with buf (kt+2)%3

        // safe: (kt+2)%3 != kt%3 (being computed) and != (kt+1)%3 (in flight)
        if (kt + 2 < SS / 64) issue_k(kt + 2);
        CP_COMMIT();

        const uint32_t* Kb = Kbuf + (kt % 3) * KBUF_WORDS;

        // ---- S = Q @ K^T ----
        float s[8][4];
        #pragma unroll
        for (int j = 0; j < 8; ++j)
            #pragma unroll
            for (int c = 0; c < 4; ++c) s[j][c] = 0.f;

        #pragma unroll
        for (int ks = 0; ks < 24; ++ks) {
            const int k0 = ks * 8;
            #pragma unroll
            for (int j = 0; j < 8; ++j) {
                const uint32_t* bbase = Kb + (8*j + gr) * ALDQ + k0 + gc;
                uint32_t b0 = bbase[0];
                uint32_t b1 = bbase[4];
                MMA_TF32(s[j][0], s[j][1], s[j][2], s[j][3],
                         qf[ks][0], qf[ks][1], qf[ks][2], qf[ks][3], b0, b1);
            }
        }

        // ---- online softmax; P stays in s[][] ----
        float mx0 = -INFINITY, mx1 = -INFINITY;
        #pragma unroll
        for (int j = 0; j < 8; ++j) {
            s[j][0] *= scale; s[j][1] *= scale; s[j][2] *= scale; s[j][3] *= scale;
            mx0 = fmaxf(mx0, fmaxf(s[j][0], s[j][1]));
            mx1 = fmaxf(mx1, fmaxf(s[j][2], s[j][3]));
        }
        #pragma unroll
        for (int off = 1; off <= 2; off <<= 1) {
            mx0 = fmaxf(mx0, __shfl_xor_sync(0xffffffffu, mx0, off));
            mx1 = fmaxf(mx1, __shfl_xor_sync(0xffffffffu, mx1, off));
        }
        float m0n = fmaxf(m0, mx0);
        float m1n = fmaxf(m1, mx1);
        float al0 = __expf(m0 - m0n);
        float al1 = __expf(m1 - m1n);
        float rs0 = 0.f, rs1 = 0.f;
        #pragma unroll
        for (int j = 0; j < 8; ++j) {
            s[j][0] = __expf(s[j][0] - m0n);
            s[j][1] = __expf(s[j][1] - m0n);
            s[j][2] = __expf(s[j][2] - m1n);
            s[j][3] = __expf(s[j][3] - m1n);
            rs0 += s[j][0] + s[j][1];
            rs1 += s[j][2] + s[j][3];
        }
        #pragma unroll
        for (int off = 1; off <= 2; off <<= 1) {
            rs0 += __shfl_xor_sync(0xffffffffu, rs0, off);
            rs1 += __shfl_xor_sync(0xffffffffu, rs1, off);
        }
        l0 = l0 * al0 + rs0;
        l1 = l1 * al1 + rs1;
        m0 = m0n; m1 = m1n;
        #pragma unroll
        for (int j = 0; j < 16; ++j) {
            o[j][0] *= al0; o[j][1] *= al0;
            o[j][2] *= al1; o[j][3] *= al1;
        }

        // ---- O += P @ V : A-fragments from registers via width-4 shuffles ----
        #pragma unroll 2
        for (int ks = 0; ks < 8; ++ks) {
            const int k0 = ks * 8;
            float v0 = __shfl_sync(0xffffffffu, s[ks][0], srcA, 4);
            float v1 = __shfl_sync(0xffffffffu, s[ks][1], srcA, 4);
            float v2 = __shfl_sync(0xffffffffu, s[ks][2], srcA, 4);
            float v3 = __shfl_sync(0xffffffffu, s[ks][3], srcA, 4);
            float w0 = __shfl_sync(0xffffffffu, s[ks][0], srcB, 4);
            float w1 = __shfl_sync(0xffffffffu, s[ks][1], srcB, 4);
            float w2 = __shfl_sync(0xffffffffu, s[ks][2], srcB, 4);
            float w3 = __shfl_sync(0xffffffffu, s[ks][3], srcB, 4);
            uint32_t a0 = f2tf32(odd ? v1 : v0);
            uint32_t a1 = f2tf32(odd ? v3 : v2);
            uint32_t a2 = f2tf32(odd ? w1 : w0);
            uint32_t a3 = f2tf32(odd ? w3 : w2);
            #pragma unroll
            for (int j = 0; j < 16; ++j) {
                uint32_t b0 = Kb[(k0 + gc) * ALDQ + 8*j + gr];
                uint32_t b1 = Kb[(k0 + gc + 4) * ALDQ + 8*j + gr];
                MMA_TF32(o[j][0], o[j][1], o[j][2], o[j][3], a0, a1, a2, a3, b0, b1);
            }
        }
        // no trailing barrier: next iteration's top barrier provides ordering
    }

    // ---- epilogue (write tf32-rounded attn for the Wo GEMM) ----
    float inv0 = 1.0f / l0;
    float inv1 = 1.0f / l1;
    size_t r0 = (tok0 + q0 + wq + gr) * DMODEL + h * DHD;
    size_t r1 = (tok0 + q0 + wq + gr + 8) * DMODEL + h * DHD;
    #pragma unroll
    for (int j = 0; j < 16; ++j) {
        int c = 8*j + 2*gc;
        *(float2*)(out + r0 + c) =
            make_float2(roundtf(o[j][0] * inv0), roundtf(o[j][1] * inv0));
        *(float2*)(out + r1 + c) =
            make_float2(roundtf(o[j][2] * inv1), roundtf(o[j][3] * inv1));
    }
}

// ================= host launch =================
static inline void launch_gemm(const float* A, int lda, const float* Bt,
                               const float* bias, float* C, int ldc,
                               int N, int K, int round_out)
{
    dim3 grid(N / 128, NTOK / 128);
    gemm_cp<<<grid, 256, GEMM_SMEM>>>(A, lda, Bt, bias, C, ldc, K, round_out);
}

extern "C" void kernel_launch(void* const* d_in, const int* in_sizes, int n_in,
                              void* d_out, int out_size)
{
    (void)in_sizes; (void)n_in; (void)out_size;
    const float* x   = (const float*)d_in[0];
    const float* Wd  = (const float*)d_in[1];
    const float* bd  = (const float*)d_in[2];
    const float* Wu  = (const float*)d_in[3];
    const float* bu  = (const float*)d_in[4];
    const float* Wqd = (const float*)d_in[5];
    const float* bqd = (const float*)d_in[6];
    const float* Wqu = (const float*)d_in[7];
    const float* bqu = (const float*)d_in[8];
    const float* Wqr = (const float*)d_in[9];
    const float* bqr = (const float*)d_in[10];
    const float* Wkr = (const float*)d_in[11];
    const float* bkr = (const float*)d_in[12];
    const float* Wo  = (const float*)d_in[13];
    const float* bo  = (const float*)d_in[14];
    float* out = (float*)d_out;

    float *xt, *big0, *kvup, *big2, *attn;
    float *bt0, *wuT, *bt2, *woT, *bias0, *bias2;
    cudaGetSymbolAddress((void**)&xt,    g_xt);
    cudaGetSymbolAddress((void**)&big0,  g_big0);
    cudaGetSymbolAddress((void**)&kvup,  g_kvup);
    cudaGetSymbolAddress((void**)&big2,  g_big2);
    cudaGetSymbolAddress((void**)&attn,  g_attn);
    cudaGetSymbolAddress((void**)&bt0,   g_bt0);
    cudaGetSymbolAddress((void**)&wuT,   g_wuT);
    cudaGetSymbolAddress((void**)&bt2,   g_bt2);
    cudaGetSymbolAddress((void**)&woT,   g_woT);
    cudaGetSymbolAddress((void**)&bias0, g_bias0);
    cudaGetSymbolAddress((void**)&bias2, g_bias2);

    cudaFuncSetAttribute(gemm_cp, cudaFuncAttributeMaxDynamicSharedMemorySize,
                         GEMM_SMEM);
    cudaFuncSetAttribute(gemm_dual, cudaFuncAttributeMaxDynamicSharedMemorySize,
                         GEMM_SMEM);
    cudaFuncSetAttribute(flash_mma, cudaFuncAttributeMaxDynamicSharedMemorySize,
                         FL_SMEM);

    // L0: pre-round x
    round_tf32_kernel<<<(NTOK*DMODEL/4 + 255)/256, 256>>>(x, xt, NTOK*DMODEL/4);
    // L1: fused transpose [Wd|Wqd|Wkr] -> bt0
    transpose_multi<<<dim3(N0/32, DMODEL/32), dim3(32, 8)>>>(
        Wd, DC, Wqd, DCOMP, Wkr, NH*DRP, bt0, DMODEL);
    // L2: bias0
    concat_bias3<<<(N0 + 255)/256, 256>>>(bias0, bd, DC, bqd, DCOMP, bkr, NH*DRP);
    // L3: G1 mega-GEMM  <-- PROFILED
    launch_gemm(xt, DMODEL, bt0, bias0, big0, N0, N0, DMODEL, 1);
    // L4: transpose Wu
    transpose_multi<<<dim3(DMODEL/32, DC/32), dim3(32, 8)>>>(
        Wu, DMODEL, Wu, 0, Wu, 0, wuT, DC);
    // L5: fused transpose [Wqu|Wqr] -> bt2
    transpose_multi<<<dim3(N2/32, DCOMP/32), dim3(32, 8)>>>(
        Wqu, DMODEL, Wqr, NH*DRP, Wqr, 0, bt2, DCOMP);
    // L6: bias2
    concat_bias3<<<(N2 + 255)/256, 256>>>(bias2, bqu, DMODEL, bqr, NH*DRP,
                                          bqr, 0);
    // L7: fused dual GEMM — kv_up + (q_c|q_r)
    {
        dim3 grid(DMODEL/128 + N2/128, NTOK/128);
        gemm_dual<<<grid, 256, GEMM_SMEM>>>(
            big0, N0, wuT, bu, kvup, DMODEL, DC,
            big0 + QCMP_OFF, N0, bt2, bias2, big2, N2, DCOMP,
            DMODEL/128);
    }
    // L8: fused rope
    {
        int n = NTOK * NH * 32;
        rope_kernel2<<<(2*n + 255)/256, 256>>>(big2, big0, n);
    }
    // L9: transpose Wo
    transpose_multi<<<dim3(DMODEL/32, DMODEL/32), dim3(32, 8)>>>(
        Wo, DMODEL, Wo, 0, Wo, 0, woT, DMODEL);
    // L10: attention
    {
        dim3 grid(SS / 128, NH, BB);
        flash_mma<<<grid, 256, FL_SMEM>>>(big2, kvup, big0, attn);
    }
    // L11: output projection
    launch_gemm(attn, DMODEL, woT, bo, out, DMODEL, DMODEL, DMODEL, 0);
}